// round 3
// baseline (speedup 1.0000x reference)
#include <cuda_runtime.h>
#include <math.h>

// ---------------------------------------------------------------------------
// TextureBaker — single fused kernel.
// Block = 16x16 pixel tile (256 threads). Per chunk of <=512 triangles:
//   1) every thread computes barycentric setup for 2 triangles directly from
//      uv/fidx (L2-hot gathers), runs a conservative tri/tile SAT test,
//   2) stable (index-ordered) ballot compaction writes surviving records
//      into shared memory,
//   3) each thread scans the smem list in order with first-hit early exit.
// Then attr gather + barycentric blend. Setup and scan arithmetic are
// expression-identical to the previously passing kernel.
// ---------------------------------------------------------------------------

#define TS        16
#define CHUNK     512   // triangles binned per smem batch

struct __align__(16) Tri {
    float ax, ay, v0x, v0y;
    float v1x, v1y, d00, d01;
    float d11, inv;
    int   i0,  i1;
    int   i2,  pad0, pad1, pad2;
};

__device__ __forceinline__ bool rect_outside_edge(
    float px, float py, float qx, float qy, float rx, float ry,
    float x0, float y0, float x1, float y1)
{
    float ex = qx - px, ey = qy - py;
    float sr  = ex * (ry - py) - ey * (rx - px);
    float s00 = ex * (y0 - py) - ey * (x0 - px);
    float s01 = ex * (y1 - py) - ey * (x0 - px);
    float s10 = ex * (y0 - py) - ey * (x1 - px);
    float s11 = ex * (y1 - py) - ey * (x1 - px);
    float mx = fmaxf(fmaxf(s00, s01), fmaxf(s10, s11));
    float mn = fminf(fminf(s00, s01), fminf(s10, s11));
    if (sr > 0.0f) return mx < 0.0f;   // whole rect strictly on far side
    if (sr < 0.0f) return mn > 0.0f;
    return false;                      // degenerate edge: keep (conservative)
}

__global__ void __launch_bounds__(256)
tb_fused_kernel(const float* __restrict__ attr,
                const float* __restrict__ uv,
                const int*   __restrict__ fidx,
                int nf, int res, int ntx,
                float* __restrict__ out)
{
    extern __shared__ Tri s_tri[];            // CHUNK records (32 KB)
    __shared__ int s_warpTot[8];
    __shared__ int s_base;

    int tile = blockIdx.x;
    int tx = tile % ntx;
    int ty = tile / ntx;
    int tid  = threadIdx.x;
    int lane = tid & 31;
    int wid  = tid >> 5;

    // tile UV bounds (eps-expanded, conservative)
    const float eps = 1e-5f;
    float rinv = 1.0f / (float)res;
    float x0 = (float)(tx * TS)      * rinv - eps;
    float x1 = (float)(tx * TS + TS) * rinv + eps;
    float y0 = (float)(ty * TS)      * rinv - eps;
    float y1 = (float)(ty * TS + TS) * rinv + eps;

    // this thread's pixel
    int col = tx * TS + (tid & (TS - 1));
    int row = ty * TS + (tid >> 4);
    bool valid = (col < res) && (row < res);
    float pxx = ((float)col + 0.5f) * rinv;
    float pxy = ((float)row + 0.5f) * rinv;

    int   hitI0 = 0, hitI1 = 0, hitI2 = 0;
    float u = 0.0f, v = 0.0f, w = 0.0f;
    bool  found = false;

    for (int chunk = 0; chunk < nf; chunk += CHUNK) {
        // ---- bin this chunk into smem (stable order) ----
        __syncthreads();                     // protect s_tri from prior scan
        if (tid == 0) s_base = 0;
        __syncthreads();

        #pragma unroll
        for (int sub = 0; sub < CHUNK; sub += 256) {
            int t = chunk + sub + tid;
            bool keep = false;
            Tri r;
            if (t < nf) {
                int i0 = fidx[3 * t + 0];
                int i1 = fidx[3 * t + 1];
                int i2 = fidx[3 * t + 2];

                float ax = uv[2 * i0], ay = uv[2 * i0 + 1];
                float bx = uv[2 * i1], by = uv[2 * i1 + 1];
                float cx = uv[2 * i2], cy = uv[2 * i2 + 1];

                float tminx = fminf(ax, fminf(bx, cx));
                float tmaxx = fmaxf(ax, fmaxf(bx, cx));
                float tminy = fminf(ay, fminf(by, cy));
                float tmaxy = fmaxf(ay, fmaxf(by, cy));

                keep = !(tminx > x1 || tmaxx < x0 || tminy > y1 || tmaxy < y0);
                if (keep) {
                    if (rect_outside_edge(ax, ay, bx, by, cx, cy, x0, y0, x1, y1) ||
                        rect_outside_edge(bx, by, cx, cy, ax, ay, x0, y0, x1, y1) ||
                        rect_outside_edge(cx, cy, ax, ay, bx, by, x0, y0, x1, y1))
                        keep = false;
                }
                if (keep) {
                    float v0x = bx - ax, v0y = by - ay;
                    float v1x = cx - ax, v1y = cy - ay;
                    float d00 = v0x * v0x + v0y * v0y;
                    float d01 = v0x * v1x + v0y * v1y;
                    float d11 = v1x * v1x + v1y * v1y;
                    float denom = d00 * d11 - d01 * d01;
                    float inv = (fabsf(denom) < 1e-12f)
                                    ? __int_as_float(0x7fc00000)   // NaN: never inside
                                    : (1.0f / denom);
                    r.ax = ax;  r.ay = ay;  r.v0x = v0x; r.v0y = v0y;
                    r.v1x = v1x; r.v1y = v1y; r.d00 = d00; r.d01 = d01;
                    r.d11 = d11; r.inv = inv;
                    r.i0 = i0; r.i1 = i1; r.i2 = i2;
                    r.pad0 = r.pad1 = r.pad2 = 0;
                }
            }

            unsigned bal = __ballot_sync(0xffffffffu, keep);
            int wpre = __popc(bal & ((1u << lane) - 1u));
            if (lane == 0) s_warpTot[wid] = __popc(bal);
            __syncthreads();

            int wbase = 0;
            #pragma unroll
            for (int k = 0; k < 8; k++) wbase += (k < wid) ? s_warpTot[k] : 0;

            if (keep) {
                int pos = s_base + wbase + wpre;
                float4* dst = (float4*)&s_tri[pos];
                const float4* src = (const float4*)&r;
                dst[0] = src[0]; dst[1] = src[1];
                dst[2] = src[2]; dst[3] = src[3];
            }
            __syncthreads();

            if (tid == 0) {
                int tot = 0;
                #pragma unroll
                for (int k = 0; k < 8; k++) tot += s_warpTot[k];
                s_base += tot;
            }
            __syncthreads();
        }

        int bn = s_base;

        // ---- scan smem list (first hit wins, early exit) ----
        if (!found && valid) {
            for (int j = 0; j < bn; j++) {
                float4 q0 = *(const float4*)&s_tri[j].ax;   // ax ay v0x v0y
                float4 q1 = *(const float4*)&s_tri[j].v1x;  // v1x v1y d00 d01
                float2 q2 = *(const float2*)&s_tri[j].d11;  // d11 inv

                float v2x = pxx - q0.x;
                float v2y = pxy - q0.y;
                float d20 = v2x * q0.z + v2y * q0.w;
                float d21 = v2x * q1.x + v2y * q1.y;
                float vv  = (q2.x * d20 - q1.w * d21) * q2.y;
                float ww  = (q1.z * d21 - q1.w * d20) * q2.y;
                float uu  = 1.0f - vv - ww;
                if (uu >= 0.0f && vv >= 0.0f && ww >= 0.0f) {
                    found = true;
                    u = uu; v = vv; w = ww;
                    hitI0 = s_tri[j].i0;
                    hitI1 = s_tri[j].i1;
                    hitI2 = s_tri[j].i2;
                    break;
                }
            }
        }
    }

    if (!valid) return;

    float o0 = 0.0f, o1 = 0.0f, o2 = 0.0f;
    if (found) {
        const float* a0 = attr + 3 * hitI0;
        const float* a1 = attr + 3 * hitI1;
        const float* a2 = attr + 3 * hitI2;
        o0 = u * a0[0] + v * a1[0] + w * a2[0];
        o1 = u * a0[1] + v * a1[1] + w * a2[1];
        o2 = u * a0[2] + v * a1[2] + w * a2[2];
    }

    int pix = row * res + col;
    out[3 * pix + 0] = o0;
    out[3 * pix + 1] = o1;
    out[3 * pix + 2] = o2;
}

extern "C" void kernel_launch(void* const* d_in, const int* in_sizes, int n_in,
                              void* d_out, int out_size)
{
    const float* attr = (const float*)d_in[0];
    const float* uv   = (const float*)d_in[1];
    const int*   fidx = (const int*)  d_in[2];
    float*       out  = (float*)      d_out;

    int nf = in_sizes[2] / 3;
    int nf_used = (nf / 64) * 64;          // reference truncates to chunks of 64

    int res = (int)(sqrt((double)out_size / 3.0) + 0.5);
    int ntx = (res + TS - 1) / TS;
    int ntiles = ntx * ntx;

    size_t smem = (size_t)CHUNK * sizeof(Tri);
    tb_fused_kernel<<<ntiles, 256, smem>>>(attr, uv, fidx, nf_used, res, ntx, out);
}

// round 4
// speedup vs baseline: 1.0152x; 1.0152x over previous
#include <cuda_runtime.h>
#include <math.h>

// ---------------------------------------------------------------------------
// TextureBaker — 2 kernels.
//  1) tb_setup : per-triangle barycentric setup -> 64B Tri record + 16B bbox.
//  2) tb_bake  : block = 16x16 pixel tile.
//       Phase A: bbox-only tri/tile rejection (coalesced float4 reads of the
//                8KB bbox table), stable ballot compaction of kept indices.
//       Phase B: coalesced copy of kept Tri records (L2-hot) into smem.
//       Phase C: per-pixel first-hit scan (early exit) + attr interpolation.
// All FP expressions identical to the previously passing kernels.
// ---------------------------------------------------------------------------

#define MAX_F  8192
#define TS     16
#define CHUNK  512

struct __align__(16) Tri {
    float ax, ay, v0x, v0y;
    float v1x, v1y, d00, d01;
    float d11, inv;
    int   i0,  i1;
    int   i2,  pad0, pad1, pad2;
};

__device__ Tri    g_tri [MAX_F];
__device__ float4 g_bbox[MAX_F];   // (minx, maxx, miny, maxy)

// ------------------------------- setup ------------------------------------
__global__ void tb_setup_kernel(const float* __restrict__ uv,
                                const int*   __restrict__ fidx,
                                int nf)
{
    int t = blockIdx.x * blockDim.x + threadIdx.x;
    if (t >= nf) return;

    int i0 = fidx[3 * t + 0];
    int i1 = fidx[3 * t + 1];
    int i2 = fidx[3 * t + 2];

    float ax = uv[2 * i0], ay = uv[2 * i0 + 1];
    float bx = uv[2 * i1], by = uv[2 * i1 + 1];
    float cx = uv[2 * i2], cy = uv[2 * i2 + 1];

    float v0x = bx - ax, v0y = by - ay;
    float v1x = cx - ax, v1y = cy - ay;

    float d00 = v0x * v0x + v0y * v0y;
    float d01 = v0x * v1x + v0y * v1y;
    float d11 = v1x * v1x + v1y * v1y;
    float denom = d00 * d11 - d01 * d01;

    // Degenerate triangle -> NaN inv -> inside test always false (matches ref).
    float inv = (fabsf(denom) < 1e-12f) ? __int_as_float(0x7fc00000)
                                        : (1.0f / denom);

    Tri r;
    r.ax = ax;  r.ay = ay;  r.v0x = v0x; r.v0y = v0y;
    r.v1x = v1x; r.v1y = v1y; r.d00 = d00; r.d01 = d01;
    r.d11 = d11; r.inv = inv;
    r.i0 = i0; r.i1 = i1; r.i2 = i2;
    r.pad0 = r.pad1 = r.pad2 = 0;
    g_tri[t] = r;

    float4 bb;
    bb.x = fminf(ax, fminf(bx, cx));   // minx
    bb.y = fmaxf(ax, fmaxf(bx, cx));   // maxx
    bb.z = fminf(ay, fminf(by, cy));   // miny
    bb.w = fmaxf(ay, fmaxf(by, cy));   // maxy
    g_bbox[t] = bb;
}

// -------------------------------- bake ------------------------------------
__global__ void __launch_bounds__(256)
tb_bake_kernel(const float* __restrict__ attr,
               int nf, int res, int ntx,
               float* __restrict__ out)
{
    __shared__ Tri s_tri[CHUNK];        // 32 KB
    __shared__ int s_idx[CHUNK];        // kept triangle ids (stable order)
    __shared__ int s_warpTot[8];
    __shared__ int s_base;

    int tile = blockIdx.x;
    int tx = tile % ntx;
    int ty = tile / ntx;
    int tid  = threadIdx.x;
    int lane = tid & 31;
    int wid  = tid >> 5;

    const float eps = 1e-5f;
    float rinv = 1.0f / (float)res;
    float x0 = (float)(tx * TS)      * rinv - eps;
    float x1 = (float)(tx * TS + TS) * rinv + eps;
    float y0 = (float)(ty * TS)      * rinv - eps;
    float y1 = (float)(ty * TS + TS) * rinv + eps;

    int col = tx * TS + (tid & (TS - 1));
    int row = ty * TS + (tid >> 4);
    bool valid = (col < res) && (row < res);
    float pxx = ((float)col + 0.5f) * rinv;
    float pxy = ((float)row + 0.5f) * rinv;

    int   hitI0 = 0, hitI1 = 0, hitI2 = 0;
    float u = 0.0f, v = 0.0f, w = 0.0f;
    bool  found = false;

    for (int chunk = 0; chunk < nf; chunk += CHUNK) {
        // ---- Phase A: bbox rejection + stable compaction of indices ----
        __syncthreads();
        if (tid == 0) s_base = 0;
        __syncthreads();

        #pragma unroll
        for (int sub = 0; sub < CHUNK; sub += 256) {
            int t = chunk + sub + tid;
            bool keep = false;
            if (t < nf) {
                float4 bb = g_bbox[t];
                keep = !(bb.x > x1 || bb.y < x0 || bb.z > y1 || bb.w < y0);
            }

            unsigned bal = __ballot_sync(0xffffffffu, keep);
            int wpre = __popc(bal & ((1u << lane) - 1u));
            if (lane == 0) s_warpTot[wid] = __popc(bal);
            __syncthreads();

            int wbase = 0;
            #pragma unroll
            for (int k = 0; k < 8; k++) wbase += (k < wid) ? s_warpTot[k] : 0;

            if (keep)
                s_idx[s_base + wbase + wpre] = t;
            __syncthreads();

            if (tid == 0) {
                int tot = 0;
                #pragma unroll
                for (int k = 0; k < 8; k++) tot += s_warpTot[k];
                s_base += tot;
            }
            __syncthreads();
        }

        int bn = s_base;

        // ---- Phase B: coalesced copy of kept records into smem ----
        for (int e = tid; e < bn * 4; e += 256) {
            int k = e >> 2;
            int q = e & 3;
            ((float4*)&s_tri[k])[q] = ((const float4*)&g_tri[s_idx[k]])[q];
        }
        __syncthreads();

        // ---- Phase C: first-hit scan (early exit) ----
        if (!found && valid) {
            for (int j = 0; j < bn; j++) {
                float4 q0 = *(const float4*)&s_tri[j].ax;   // ax ay v0x v0y
                float4 q1 = *(const float4*)&s_tri[j].v1x;  // v1x v1y d00 d01
                float2 q2 = *(const float2*)&s_tri[j].d11;  // d11 inv

                float v2x = pxx - q0.x;
                float v2y = pxy - q0.y;
                float d20 = v2x * q0.z + v2y * q0.w;
                float d21 = v2x * q1.x + v2y * q1.y;
                float vv  = (q2.x * d20 - q1.w * d21) * q2.y;
                float ww  = (q1.z * d21 - q1.w * d20) * q2.y;
                float uu  = 1.0f - vv - ww;
                if (uu >= 0.0f && vv >= 0.0f && ww >= 0.0f) {
                    found = true;
                    u = uu; v = vv; w = ww;
                    hitI0 = s_tri[j].i0;
                    hitI1 = s_tri[j].i1;
                    hitI2 = s_tri[j].i2;
                    break;
                }
            }
        }
    }

    if (!valid) return;

    float o0 = 0.0f, o1 = 0.0f, o2 = 0.0f;
    if (found) {
        const float* a0 = attr + 3 * hitI0;
        const float* a1 = attr + 3 * hitI1;
        const float* a2 = attr + 3 * hitI2;
        o0 = u * a0[0] + v * a1[0] + w * a2[0];
        o1 = u * a0[1] + v * a1[1] + w * a2[1];
        o2 = u * a0[2] + v * a1[2] + w * a2[2];
    }

    int pix = row * res + col;
    out[3 * pix + 0] = o0;
    out[3 * pix + 1] = o1;
    out[3 * pix + 2] = o2;
}

// ------------------------------- launch -----------------------------------
extern "C" void kernel_launch(void* const* d_in, const int* in_sizes, int n_in,
                              void* d_out, int out_size)
{
    const float* attr = (const float*)d_in[0];
    const float* uv   = (const float*)d_in[1];
    const int*   fidx = (const int*)  d_in[2];
    float*       out  = (float*)      d_out;

    int nf = in_sizes[2] / 3;
    int nf_used = (nf / 64) * 64;          // reference truncates to chunks of 64
    if (nf_used > MAX_F) nf_used = MAX_F;

    int res = (int)(sqrt((double)out_size / 3.0) + 0.5);
    int ntx = (res + TS - 1) / TS;
    int ntiles = ntx * ntx;

    if (nf_used > 0) {
        int sblocks = (nf_used + 255) / 256;
        tb_setup_kernel<<<sblocks, 256>>>(uv, fidx, nf_used);
    }
    tb_bake_kernel<<<ntiles, 256>>>(attr, nf_used, res, ntx, out);
}

// round 5
// speedup vs baseline: 1.1404x; 1.1234x over previous
#include <cuda_runtime.h>
#include <math.h>

// ---------------------------------------------------------------------------
// TextureBaker — 2 kernels.
//  1) tb_setup : per-triangle barycentric setup -> 64B Tri record + 16B bbox.
//  2) tb_bake  : block = 16x16 pixel tile.
//       Phase A : bbox rejection of all triangles (coalesced float4 reads),
//                 single combined stable compaction (2 barriers).
//       Phase A2: SAT (3 edge half-plane) refine on bbox survivors only,
//                 stable compaction again.
//       Phase B : coalesced copy of refined records (L2-hot) into smem.
//       Phase C : per-pixel first-hit scan (early exit) + attr interpolation.
// Scan FP expressions identical to the previously passing kernels.
// ---------------------------------------------------------------------------

#define MAX_F  8192
#define TS     16
#define SCAP   256     // records per smem batch in phase B/C

struct __align__(16) Tri {
    float ax, ay, v0x, v0y;
    float v1x, v1y, d00, d01;
    float d11, inv;
    int   i0,  i1;
    int   i2,  pad0, pad1, pad2;
};

__device__ Tri    g_tri [MAX_F];
__device__ float4 g_bbox[MAX_F];   // (minx, maxx, miny, maxy)

// ------------------------------- setup ------------------------------------
__global__ void tb_setup_kernel(const float* __restrict__ uv,
                                const int*   __restrict__ fidx,
                                int nf)
{
    int t = blockIdx.x * blockDim.x + threadIdx.x;
    if (t >= nf) return;

    int i0 = fidx[3 * t + 0];
    int i1 = fidx[3 * t + 1];
    int i2 = fidx[3 * t + 2];

    float ax = uv[2 * i0], ay = uv[2 * i0 + 1];
    float bx = uv[2 * i1], by = uv[2 * i1 + 1];
    float cx = uv[2 * i2], cy = uv[2 * i2 + 1];

    float v0x = bx - ax, v0y = by - ay;
    float v1x = cx - ax, v1y = cy - ay;

    float d00 = v0x * v0x + v0y * v0y;
    float d01 = v0x * v1x + v0y * v1y;
    float d11 = v1x * v1x + v1y * v1y;
    float denom = d00 * d11 - d01 * d01;

    // Degenerate triangle -> NaN inv -> inside test always false (matches ref).
    float inv = (fabsf(denom) < 1e-12f) ? __int_as_float(0x7fc00000)
                                        : (1.0f / denom);

    Tri r;
    r.ax = ax;  r.ay = ay;  r.v0x = v0x; r.v0y = v0y;
    r.v1x = v1x; r.v1y = v1y; r.d00 = d00; r.d01 = d01;
    r.d11 = d11; r.inv = inv;
    r.i0 = i0; r.i1 = i1; r.i2 = i2;
    r.pad0 = r.pad1 = r.pad2 = 0;
    g_tri[t] = r;

    float4 bb;
    bb.x = fminf(ax, fminf(bx, cx));
    bb.y = fmaxf(ax, fmaxf(bx, cx));
    bb.z = fminf(ay, fminf(by, cy));
    bb.w = fmaxf(ay, fmaxf(by, cy));
    g_bbox[t] = bb;
}

// ----------------------------- SAT helper ---------------------------------
__device__ __forceinline__ bool rect_outside_edge(
    float px, float py, float qx, float qy, float rx, float ry,
    float x0, float y0, float x1, float y1)
{
    float ex = qx - px, ey = qy - py;
    float sr  = ex * (ry - py) - ey * (rx - px);
    float s00 = ex * (y0 - py) - ey * (x0 - px);
    float s01 = ex * (y1 - py) - ey * (x0 - px);
    float s10 = ex * (y0 - py) - ey * (x1 - px);
    float s11 = ex * (y1 - py) - ey * (x1 - px);
    float mx = fmaxf(fmaxf(s00, s01), fmaxf(s10, s11));
    float mn = fminf(fminf(s00, s01), fminf(s10, s11));
    if (sr > 0.0f) return mx < 0.0f;   // whole rect strictly on far side
    if (sr < 0.0f) return mn > 0.0f;
    return false;                      // degenerate edge: keep (conservative)
}

// -------------------------------- bake ------------------------------------
__global__ void __launch_bounds__(256)
tb_bake_kernel(const float* __restrict__ attr,
               int nf, int res, int ntx,
               float* __restrict__ out)
{
    __shared__ Tri s_tri[SCAP];       // 16 KB
    __shared__ int s_idx [512];       // bbox survivors (stable order)
    __shared__ int s_idx2[512];       // SAT survivors (stable order)
    __shared__ int s_tot[16];

    int tile = blockIdx.x;
    int tx = tile % ntx;
    int ty = tile / ntx;
    int tid  = threadIdx.x;
    int lane = tid & 31;
    int wid  = tid >> 5;
    unsigned lmask = (1u << lane) - 1u;

    const float eps = 1e-5f;
    float rinv = 1.0f / (float)res;
    float x0 = (float)(tx * TS)      * rinv - eps;
    float x1 = (float)(tx * TS + TS) * rinv + eps;
    float y0 = (float)(ty * TS)      * rinv - eps;
    float y1 = (float)(ty * TS + TS) * rinv + eps;

    int col = tx * TS + (tid & (TS - 1));
    int row = ty * TS + (tid >> 4);
    bool valid = (col < res) && (row < res);
    float pxx = ((float)col + 0.5f) * rinv;
    float pxy = ((float)row + 0.5f) * rinv;

    // ---- Phase A: bbox rejection (two 256-wide sub-chunks, one prefix) ----
    // NOTE: assumes nf <= 512 (true here: nf = 512). Generalized below by an
    // outer loop over 512-sized chunks.
    int   hitI0 = 0, hitI1 = 0, hitI2 = 0;
    float u = 0.0f, v = 0.0f, w = 0.0f;
    bool  found = false;

    for (int chunk = 0; chunk < nf; chunk += 512) {
        __syncthreads();

        int t0 = chunk + tid;
        int t1 = chunk + 256 + tid;
        bool k0 = false, k1 = false;
        if (t0 < nf) {
            float4 bb = g_bbox[t0];
            k0 = !(bb.x > x1 || bb.y < x0 || bb.z > y1 || bb.w < y0);
        }
        if (t1 < nf) {
            float4 bb = g_bbox[t1];
            k1 = !(bb.x > x1 || bb.y < x0 || bb.z > y1 || bb.w < y0);
        }
        unsigned b0 = __ballot_sync(0xffffffffu, k0);
        unsigned b1 = __ballot_sync(0xffffffffu, k1);
        if (lane == 0) { s_tot[wid] = __popc(b0); s_tot[8 + wid] = __popc(b1); }
        __syncthreads();

        int pre0 = 0, tot0 = 0, pre1 = 0, tot1 = 0;
        #pragma unroll
        for (int k = 0; k < 8; k++) {
            int a = s_tot[k], b = s_tot[8 + k];
            tot0 += a; tot1 += b;
            pre0 += (k < wid) ? a : 0;
            pre1 += (k < wid) ? b : 0;
        }
        if (k0) s_idx[pre0 + __popc(b0 & lmask)] = t0;
        if (k1) s_idx[tot0 + pre1 + __popc(b1 & lmask)] = t1;
        __syncthreads();
        int bn = tot0 + tot1;

        // ---- Phase A2: SAT refine on survivors ----
        int bn2 = 0;
        for (int base = 0; base < bn; base += 256) {
            int  e = base + tid;
            bool keep = false;
            if (e < bn) {
                int t = s_idx[e];
                float4 a4 = ((const float4*)&g_tri[t])[0];   // ax ay v0x v0y
                float2 b2 = *(const float2*)&g_tri[t].v1x;   // v1x v1y
                float ax = a4.x,        ay = a4.y;
                float bx = ax + a4.z,   by = ay + a4.w;
                float cx = ax + b2.x,   cy = ay + b2.y;
                keep = !(rect_outside_edge(ax, ay, bx, by, cx, cy, x0, y0, x1, y1) ||
                         rect_outside_edge(bx, by, cx, cy, ax, ay, x0, y0, x1, y1) ||
                         rect_outside_edge(cx, cy, ax, ay, bx, by, x0, y0, x1, y1));
            }
            unsigned bal = __ballot_sync(0xffffffffu, keep);
            if (lane == 0) s_tot[wid] = __popc(bal);
            __syncthreads();
            int pre = 0, tot = 0;
            #pragma unroll
            for (int k = 0; k < 8; k++) {
                int a = s_tot[k];
                tot += a;
                pre += (k < wid) ? a : 0;
            }
            if (keep) s_idx2[bn2 + pre + __popc(bal & lmask)] = s_idx[e];
            __syncthreads();
            bn2 += tot;
        }

        // ---- Phase B + C: batched copy + first-hit scan ----
        for (int base = 0; base < bn2; base += SCAP) {
            int m = min(SCAP, bn2 - base);

            __syncthreads();
            for (int e = tid; e < m * 4; e += 256) {
                int k = e >> 2;
                int q = e & 3;
                ((float4*)&s_tri[k])[q] = ((const float4*)&g_tri[s_idx2[base + k]])[q];
            }
            __syncthreads();

            if (!found && valid) {
                for (int j = 0; j < m; j++) {
                    float4 q0 = *(const float4*)&s_tri[j].ax;   // ax ay v0x v0y
                    float4 q1 = *(const float4*)&s_tri[j].v1x;  // v1x v1y d00 d01
                    float2 q2 = *(const float2*)&s_tri[j].d11;  // d11 inv

                    float v2x = pxx - q0.x;
                    float v2y = pxy - q0.y;
                    float d20 = v2x * q0.z + v2y * q0.w;
                    float d21 = v2x * q1.x + v2y * q1.y;
                    float vv  = (q2.x * d20 - q1.w * d21) * q2.y;
                    float ww  = (q1.z * d21 - q1.w * d20) * q2.y;
                    float uu  = 1.0f - vv - ww;
                    if (uu >= 0.0f && vv >= 0.0f && ww >= 0.0f) {
                        found = true;
                        u = uu; v = vv; w = ww;
                        hitI0 = s_tri[j].i0;
                        hitI1 = s_tri[j].i1;
                        hitI2 = s_tri[j].i2;
                        break;
                    }
                }
            }
            // whole-block early exit when every pixel has its hit
            if (__syncthreads_and(found || !valid)) { base = bn2; }
        }
        if (__syncthreads_and(found || !valid)) break;
    }

    if (!valid) return;

    float o0 = 0.0f, o1 = 0.0f, o2 = 0.0f;
    if (found) {
        const float* a0 = attr + 3 * hitI0;
        const float* a1 = attr + 3 * hitI1;
        const float* a2 = attr + 3 * hitI2;
        o0 = u * a0[0] + v * a1[0] + w * a2[0];
        o1 = u * a0[1] + v * a1[1] + w * a2[1];
        o2 = u * a0[2] + v * a1[2] + w * a2[2];
    }

    int pix = row * res + col;
    out[3 * pix + 0] = o0;
    out[3 * pix + 1] = o1;
    out[3 * pix + 2] = o2;
}

// ------------------------------- launch -----------------------------------
extern "C" void kernel_launch(void* const* d_in, const int* in_sizes, int n_in,
                              void* d_out, int out_size)
{
    const float* attr = (const float*)d_in[0];
    const float* uv   = (const float*)d_in[1];
    const int*   fidx = (const int*)  d_in[2];
    float*       out  = (float*)      d_out;

    int nf = in_sizes[2] / 3;
    int nf_used = (nf / 64) * 64;          // reference truncates to chunks of 64
    if (nf_used > MAX_F) nf_used = MAX_F;

    int res = (int)(sqrt((double)out_size / 3.0) + 0.5);
    int ntx = (res + TS - 1) / TS;
    int ntiles = ntx * ntx;

    if (nf_used > 0) {
        int sblocks = (nf_used + 127) / 128;
        tb_setup_kernel<<<sblocks, 128>>>(uv, fidx, nf_used);
    }
    tb_bake_kernel<<<ntiles, 256>>>(attr, nf_used, res, ntx, out);
}